// round 4
// baseline (speedup 1.0000x reference)
#include <cuda_runtime.h>
#include <math.h>

// Fused single-kernel version.
//   yout = tanh(yin @ (w + alpha*hebb) + input)   [1, N]
//   hebb' = (1-eta)*hebb + eta*outer(yin, yout)   [N, N]
//
// Each CTA owns 8 contiguous columns (one 32B DRAM sector per row):
//   Phase A: full column reduction over all 4096 rows (w/alpha streamed
//            evict-first; hebb cached normally -> stays in L2).
//   Phase B: CTA-local tree reduction + tanh -> yout (write to d_out).
//   Phase C: re-walk the same hebb stripe (L2-resident) for the update.
// Single wave: 512 CTAs x 512 threads, no inter-CTA dependencies.

#define N 4096
#define COLS 8                       // columns per CTA (8 x 4B = 32B sector)
#define THREADS 512
#define CPAIRS (COLS / 2)            // 4 float2 column-pairs
#define RGROUPS (THREADS / CPAIRS)   // 128 row groups
#define ITERS (N / RGROUPS)          // 32 rows per thread

__global__ void __launch_bounds__(THREADS) k_fused(
    const float* __restrict__ input,
    const float* __restrict__ yin,
    const float* __restrict__ hebb,
    const float* __restrict__ w,
    const float* __restrict__ alpha,
    const float* __restrict__ eta,
    float* __restrict__ out)          // [yout | hebb_new]
{
    __shared__ float2 red[RGROUPS][CPAIRS];
    __shared__ float2 s_yout[CPAIRS];

    const int t  = threadIdx.x;
    const int cp = t & (CPAIRS - 1);       // column pair 0..3
    const int r  = t >> 2;                 // row group 0..127
    const int j0 = blockIdx.x * COLS;      // CTA's first column
    const int j  = j0 + cp * 2;            // this thread's column pair

    // ---------------- Phase A: column partial sums ----------------
    float2 acc = make_float2(0.f, 0.f);
    {
        const float2* __restrict__ wp = reinterpret_cast<const float2*>(w     + (size_t)r * N + j);
        const float2* __restrict__ ap = reinterpret_cast<const float2*>(alpha + (size_t)r * N + j);
        const float2* __restrict__ hp = reinterpret_cast<const float2*>(hebb  + (size_t)r * N + j);
        const size_t stride2 = (size_t)RGROUPS * (N / 2);   // 128 rows in float2 units

        #pragma unroll 8
        for (int k = 0; k < ITERS; ++k) {
            const float  y  = __ldg(&yin[r + k * RGROUPS]);
            const float2 w2 = __ldcs(wp);   // evict-first: keep L2 for hebb
            const float2 a2 = __ldcs(ap);   // evict-first
            const float2 h2 = __ldg(hp);    // default: hebb stays in L2
            acc.x = fmaf(y, fmaf(a2.x, h2.x, w2.x), acc.x);
            acc.y = fmaf(y, fmaf(a2.y, h2.y, w2.y), acc.y);
            wp += stride2; ap += stride2; hp += stride2;
        }
    }

    // ---------------- Phase B: CTA reduction + tanh ----------------
    red[r][cp] = acc;
    __syncthreads();

    #pragma unroll
    for (int s = RGROUPS / 2; s >= 1; s >>= 1) {
        if (r < s) {
            float2 o = red[r + s][cp];
            float2 m = red[r][cp];
            m.x += o.x; m.y += o.y;
            red[r][cp] = m;
        }
        __syncthreads();
    }

    if (r == 0) {
        const float2 sum = red[0][cp];
        float2 yo;
        yo.x = tanhf(sum.x + __ldg(&input[j]));
        yo.y = tanhf(sum.y + __ldg(&input[j + 1]));
        s_yout[cp] = yo;
        *reinterpret_cast<float2*>(out + j) = yo;   // yout section of d_out
    }
    __syncthreads();

    // ---------------- Phase C: hebb update (hebb from L2) ----------------
    const float  e   = __ldg(eta);
    const float  ome = 1.f - e;
    const float2 yo  = s_yout[cp];

    const float2* __restrict__ hp = reinterpret_cast<const float2*>(hebb + (size_t)r * N + j);
    float2* __restrict__ op = reinterpret_cast<float2*>(out + N + (size_t)r * N + j);
    const size_t stride2 = (size_t)RGROUPS * (N / 2);

    #pragma unroll 8
    for (int k = 0; k < ITERS; ++k) {
        const float  yie = __ldg(&yin[r + k * RGROUPS]) * e;
        const float2 h2  = __ldg(hp);        // should hit L2 (read in phase A)
        float2 r2;
        r2.x = fmaf(ome, h2.x, yie * yo.x);
        r2.y = fmaf(ome, h2.y, yie * yo.y);
        __stcs(op, r2);                      // evict-first write
        hp += stride2; op += stride2;
    }
}

extern "C" void kernel_launch(void* const* d_in, const int* in_sizes, int n_in,
                              void* d_out, int out_size)
{
    const float* input = (const float*)d_in[0];
    const float* yin   = (const float*)d_in[1];
    const float* hebb  = (const float*)d_in[2];
    const float* w     = (const float*)d_in[3];
    const float* alpha = (const float*)d_in[4];
    const float* eta   = (const float*)d_in[5];

    k_fused<<<N / COLS, THREADS>>>(input, yin, hebb, w, alpha, eta, (float*)d_out);
}

// round 6
// speedup vs baseline: 1.1551x; 1.1551x over previous
#include <cuda_runtime.h>
#include <math.h>

// 3-kernel structure with L2 eviction-priority steering via createpolicy +
// ld.global.nc.L2::cache_hint (the form ptxas accepts for .v4.f32 on sm_103a).
//   k1: split-K matvec partials. hebb -> evict_last (pin in L2),
//       w/alpha -> evict_first (stream through).
//   k2: reduce partials + tanh -> yout.
//   k3: hebb update; hebb read should hit L2, output streamed (st.cs).

#define N 4096
#define SPLITS 512             // row splits (split-K)
#define ROWS_PER (N / SPLITS)  // 8 rows per split
#define MV_THREADS 256         // each thread owns 4 columns
#define COL_BLOCKS (N / (MV_THREADS * 4))  // 4

// Deterministic split-K scratch (8 MB). No atomics -> bit-identical replays.
__device__ float g_partial[SPLITS * N];

// ---- L2 policy helpers ----
__device__ __forceinline__ unsigned long long policy_evict_first() {
    unsigned long long p;
    asm("createpolicy.fractional.L2::evict_first.b64 %0, 1.0;" : "=l"(p));
    return p;
}
__device__ __forceinline__ unsigned long long policy_evict_last() {
    unsigned long long p;
    asm("createpolicy.fractional.L2::evict_last.b64 %0, 1.0;" : "=l"(p));
    return p;
}
__device__ __forceinline__ float4 ld_hint(const float4* p, unsigned long long pol) {
    float4 v;
    asm volatile("ld.global.nc.L2::cache_hint.v4.f32 {%0,%1,%2,%3}, [%4], %5;"
                 : "=f"(v.x), "=f"(v.y), "=f"(v.z), "=f"(v.w)
                 : "l"(p), "l"(pol));
    return v;
}
__device__ __forceinline__ void st_streaming(float4* p, float4 v) {
    asm volatile("st.global.cs.v4.f32 [%0], {%1,%2,%3,%4};"
                 :: "l"(p), "f"(v.x), "f"(v.y), "f"(v.z), "f"(v.w));
}

// ---------------------------------------------------------------------------
// Kernel 1: partial matvec. 2048 CTAs; 8 fully-unrolled rows x 3 independent
// float4 loads per thread = deep MLP.
// ---------------------------------------------------------------------------
__global__ void __launch_bounds__(MV_THREADS) k_matvec_partial(
    const float* __restrict__ yin,
    const float* __restrict__ w,
    const float* __restrict__ alpha,
    const float* __restrict__ hebb)
{
    const int j  = blockIdx.x * (MV_THREADS * 4) + threadIdx.x * 4;
    const int r0 = blockIdx.y * ROWS_PER;

    const unsigned long long pol_ef = policy_evict_first();
    const unsigned long long pol_el = policy_evict_last();

    const float4* __restrict__ wp = reinterpret_cast<const float4*>(w     + (size_t)r0 * N + j);
    const float4* __restrict__ ap = reinterpret_cast<const float4*>(alpha + (size_t)r0 * N + j);
    const float4* __restrict__ hp = reinterpret_cast<const float4*>(hebb  + (size_t)r0 * N + j);
    const int stride4 = N / 4;

    float4 acc = make_float4(0.f, 0.f, 0.f, 0.f);

    #pragma unroll
    for (int i = 0; i < ROWS_PER; ++i) {
        const float  y  = __ldg(&yin[r0 + i]);
        const float4 w4 = ld_hint(wp + (size_t)i * stride4, pol_ef);
        const float4 a4 = ld_hint(ap + (size_t)i * stride4, pol_ef);
        const float4 h4 = ld_hint(hp + (size_t)i * stride4, pol_el);
        acc.x = fmaf(y, fmaf(a4.x, h4.x, w4.x), acc.x);
        acc.y = fmaf(y, fmaf(a4.y, h4.y, w4.y), acc.y);
        acc.z = fmaf(y, fmaf(a4.z, h4.z, w4.z), acc.z);
        acc.w = fmaf(y, fmaf(a4.w, h4.w, w4.w), acc.w);
    }

    *reinterpret_cast<float4*>(&g_partial[(size_t)blockIdx.y * N + j]) = acc;
}

// ---------------------------------------------------------------------------
// Kernel 2: reduce SPLITS partials, add input, tanh -> yout (d_out[0:N]).
// ---------------------------------------------------------------------------
__global__ void k_reduce_tanh(const float* __restrict__ input,
                              float* __restrict__ out_yout)
{
    const int j = blockIdx.x * blockDim.x + threadIdx.x;
    if (j >= N) return;
    float s = 0.f;
    #pragma unroll 16
    for (int p = 0; p < SPLITS; ++p)
        s += g_partial[(size_t)p * N + j];
    out_yout[j] = tanhf(s + input[j]);
}

// ---------------------------------------------------------------------------
// Kernel 3: hebb' = (1-eta)*hebb + eta*yin[i]*yout[j].
// hebb read evict_first (last consumer; should hit L2 from k1's pin);
// output streamed with st.cs.
// ---------------------------------------------------------------------------
__global__ void __launch_bounds__(256) k_hebb_update(
    const float* __restrict__ hebb,
    const float* __restrict__ yin,
    const float* __restrict__ yout,   // = d_out
    const float* __restrict__ eta,
    float* __restrict__ out_hebb)     // = d_out + N
{
    const size_t t   = (size_t)blockIdx.x * blockDim.x + threadIdx.x;
    const size_t idx = t * 4;                 // element index in N*N
    const int i = (int)(idx >> 12);           // row (N = 2^12)
    const int j = (int)(idx & (N - 1));       // col

    const unsigned long long pol_ef = policy_evict_first();

    const float e   = eta[0];
    const float ome = 1.f - e;
    const float yie = yin[i] * e;             // warp-uniform broadcast

    const float4 h  = ld_hint(reinterpret_cast<const float4*>(hebb + idx), pol_ef);
    const float4 yo = __ldg(reinterpret_cast<const float4*>(yout + j));

    float4 r;
    r.x = fmaf(ome, h.x, yie * yo.x);
    r.y = fmaf(ome, h.y, yie * yo.y);
    r.z = fmaf(ome, h.z, yie * yo.z);
    r.w = fmaf(ome, h.w, yie * yo.w);

    st_streaming(reinterpret_cast<float4*>(out_hebb + idx), r);
}

extern "C" void kernel_launch(void* const* d_in, const int* in_sizes, int n_in,
                              void* d_out, int out_size)
{
    const float* input = (const float*)d_in[0];
    const float* yin   = (const float*)d_in[1];
    const float* hebb  = (const float*)d_in[2];
    const float* w     = (const float*)d_in[3];
    const float* alpha = (const float*)d_in[4];
    const float* eta   = (const float*)d_in[5];

    float* out      = (float*)d_out;
    float* out_yout = out;
    float* out_hebb = out + N;

    dim3 g1(COL_BLOCKS, SPLITS);   // 4 x 512 = 2048 CTAs
    k_matvec_partial<<<g1, MV_THREADS>>>(yin, w, alpha, hebb);

    k_reduce_tanh<<<(N + 255) / 256, 256>>>(input, out_yout);

    const int hb_blocks = (N * N) / (4 * 256);
    k_hebb_update<<<hb_blocks, 256>>>(hebb, yin, out_yout, eta, out_hebb);
}